// round 4
// baseline (speedup 1.0000x reference)
#include <cuda_runtime.h>

// IF spiking neuron, T=4. Pure streaming: 128 MiB in + 128 MiB out.
// R4: persistent grid-stride version of R1. One wave (148 SMs x 8 CTAs);
// each thread loops over ~7 float4 lanes, 4 independent strided loads per
// iteration (MLP=4). Removes 6 wave transitions + per-CTA prologue costs,
// and pipelines next-iter loads under current-iter stores.

#define TSTEPS 4
#define NSM    148
#define CTAS_PER_SM 8

__global__ __launch_bounds__(256)
void if_kernel(const float4* __restrict__ x,
               const float*  __restrict__ thresh,
               float4* __restrict__ out,
               int n4, int stride4)
{
    const float th = __ldg(thresh);
    const float m0 = 0.5f * th;

    int gstride = gridDim.x * blockDim.x;

    for (int i = blockIdx.x * blockDim.x + threadIdx.x; i < n4; i += gstride) {
        // Batch 4 independent strided loads (MLP=4 per thread per iter).
        float4 xt[TSTEPS];
#pragma unroll
        for (int t = 0; t < TSTEPS; t++)
            xt[t] = x[i + t * stride4];

        float4 sp[TSTEPS];
        float* xf = reinterpret_cast<float*>(xt);
        float* sf = reinterpret_cast<float*>(sp);

        // Per-component sequential membrane recurrence (4 independent chains).
#pragma unroll
        for (int c = 0; c < 4; c++) {
            float m = m0;
#pragma unroll
            for (int t = 0; t < TSTEPS; t++) {
                m += xf[t * 4 + c];
                float s = (m >= th) ? th : 0.0f;
                sf[t * 4 + c] = s;
                m -= s;
            }
        }

#pragma unroll
        for (int t = 0; t < TSTEPS; t++)
            out[i + t * stride4] = sp[t];
    }
}

extern "C" void kernel_launch(void* const* d_in, const int* in_sizes, int n_in,
                              void* d_out, int out_size)
{
    const float* x      = (const float*)d_in[0];
    const float* thresh = (const float*)d_in[1];
    float* out          = (float*)d_out;

    int n = in_sizes[0];              // total elements (T * B*C*H*W)
    int stride = n / TSTEPS;          // elements per timestep slab
    int stride4 = stride / 4;         // float4 units per slab
    int n4 = stride4;

    int threads = 256;
    int blocks = NSM * CTAS_PER_SM;   // 1184: one full-occupancy wave
    if_kernel<<<blocks, threads>>>(
        (const float4*)x, thresh, (float4*)out, n4, stride4);
}

// round 5
// speedup vs baseline: 1.0546x; 1.0546x over previous
#include <cuda_runtime.h>

// IF spiking neuron, T=4. Pure streaming: 128 MiB in + 128 MiB out.
// R5: MLP=8 per thread (2 float4 lanes x 4 timesteps) WITHOUT the register
// cap that broke R2. No __launch_bounds__ min-blocks clause -> ptxas free to
// use ~48 regs and keep all 8 loads in flight. Plain loads/stores (stcs was
// proven neutral, ldcs untested alone -> keep default).

#define TSTEPS 4
#define LANES  2

__global__ __launch_bounds__(256)
void if_kernel(const float4* __restrict__ x,
               const float*  __restrict__ thresh,
               float4* __restrict__ out,
               int stride4)
{
    int base = blockIdx.x * (blockDim.x * LANES) + threadIdx.x;

    const float th = __ldg(thresh);
    const float m0 = 0.5f * th;

    // Batch all 8 independent strided loads up-front (MLP=8 per thread).
    float4 xt[LANES][TSTEPS];
#pragma unroll
    for (int l = 0; l < LANES; l++) {
        int idx = base + l * blockDim.x;
#pragma unroll
        for (int t = 0; t < TSTEPS; t++)
            xt[l][t] = x[idx + t * stride4];
    }

    float4 sp[LANES][TSTEPS];

#pragma unroll
    for (int l = 0; l < LANES; l++) {
        float* xf = reinterpret_cast<float*>(xt[l]);
        float* sf = reinterpret_cast<float*>(sp[l]);
#pragma unroll
        for (int c = 0; c < 4; c++) {
            float m = m0;
#pragma unroll
            for (int t = 0; t < TSTEPS; t++) {
                m += xf[t * 4 + c];
                float s = (m >= th) ? th : 0.0f;
                sf[t * 4 + c] = s;
                m -= s;
            }
        }
    }

#pragma unroll
    for (int l = 0; l < LANES; l++) {
        int idx = base + l * blockDim.x;
#pragma unroll
        for (int t = 0; t < TSTEPS; t++)
            out[idx + t * stride4] = sp[l][t];
    }
}

extern "C" void kernel_launch(void* const* d_in, const int* in_sizes, int n_in,
                              void* d_out, int out_size)
{
    const float* x      = (const float*)d_in[0];
    const float* thresh = (const float*)d_in[1];
    float* out          = (float*)d_out;

    int n = in_sizes[0];              // total elements (T * B*C*H*W) = 2^27
    int stride = n / TSTEPS;          // elements per timestep slab
    int stride4 = stride / 4;         // float4 units per slab = 2097152

    int threads = 256;
    int blocks = stride4 / (threads * LANES);   // 4096, exact division
    if_kernel<<<blocks, threads>>>(
        (const float4*)x, thresh, (float4*)out, stride4);
}

// round 6
// speedup vs baseline: 1.0949x; 1.0383x over previous
#include <cuda_runtime.h>

// IF spiking neuron, T=4. Pure streaming: 128 MiB in + 128 MiB out.
// R6: R1 structure but with 256-bit vector memory ops (sm_100+ ld/st.global.v8.f32
// -> LDG.E.256 / STG.E.256). One thread = one 32-byte lane across 4 timestep
// slabs: 4 independent 32B loads in flight (128B/thread), half the instruction
// count of R1 per byte. Spikes computed in-place over the loaded registers.

#define TSTEPS 4

struct __align__(32) f8 { float v[8]; };

__device__ __forceinline__ f8 ldg256(const f8* p) {
    f8 r;
    asm volatile("ld.global.v8.f32 {%0,%1,%2,%3,%4,%5,%6,%7}, [%8];"
                 : "=f"(r.v[0]), "=f"(r.v[1]), "=f"(r.v[2]), "=f"(r.v[3]),
                   "=f"(r.v[4]), "=f"(r.v[5]), "=f"(r.v[6]), "=f"(r.v[7])
                 : "l"(p));
    return r;
}

__device__ __forceinline__ void stg256(f8* p, const f8& r) {
    asm volatile("st.global.v8.f32 [%0], {%1,%2,%3,%4,%5,%6,%7,%8};"
                 :: "l"(p),
                    "f"(r.v[0]), "f"(r.v[1]), "f"(r.v[2]), "f"(r.v[3]),
                    "f"(r.v[4]), "f"(r.v[5]), "f"(r.v[6]), "f"(r.v[7])
                 : "memory");
}

__global__ __launch_bounds__(256)
void if_kernel(const f8* __restrict__ x,
               const float* __restrict__ thresh,
               f8* __restrict__ out,
               int stride8)
{
    int i = blockIdx.x * blockDim.x + threadIdx.x;

    const float th = __ldg(thresh);
    const float m0 = 0.5f * th;

    // Batch 4 independent strided 32B loads (128B in flight per thread).
    f8 xt[TSTEPS];
#pragma unroll
    for (int t = 0; t < TSTEPS; t++)
        xt[t] = ldg256(&x[i + t * stride8]);

    // In-place membrane recurrence: 8 independent scalar chains.
#pragma unroll
    for (int c = 0; c < 8; c++) {
        float m = m0;
#pragma unroll
        for (int t = 0; t < TSTEPS; t++) {
            m += xt[t].v[c];
            float s = (m >= th) ? th : 0.0f;
            xt[t].v[c] = s;
            m -= s;
        }
    }

#pragma unroll
    for (int t = 0; t < TSTEPS; t++)
        stg256(&out[i + t * stride8], xt[t]);
}

extern "C" void kernel_launch(void* const* d_in, const int* in_sizes, int n_in,
                              void* d_out, int out_size)
{
    const float* x      = (const float*)d_in[0];
    const float* thresh = (const float*)d_in[1];
    float* out          = (float*)d_out;

    int n = in_sizes[0];              // total elements = 2^27
    int stride = n / TSTEPS;          // elements per timestep slab = 8388608
    int stride8 = stride / 8;         // f8 units per slab = 1048576

    int threads = 256;
    int blocks = stride8 / threads;   // 4096, exact
    if_kernel<<<blocks, threads>>>(
        (const f8*)x, thresh, (f8*)out, stride8);
}